// round 17
// baseline (speedup 1.0000x reference)
#include <cuda_runtime.h>

namespace {

constexpr int H = 4096, W = 4096;
constexpr int ROWS = 16;            // output rows per block
constexpr int WPB  = 4;             // warps per block
constexpr int CPW  = 128;           // cols per warp (32 lanes x 4)
constexpr int CPB  = WPB * CPW;     // 512 cols per block
constexpr int NT   = WPB * 32;

__device__ __forceinline__ float Af(float t, float m, float b) {
    return __fadd_rn(__fmaf_rn(2.0f, m, t), b);     // t + 2m + b (2m exact)
}
__device__ __forceinline__ float GyF(float l, float c, float r) {
    return __fadd_rn(__fmaf_rn(2.0f, c, l), r);     // l + 2c + r
}
__device__ __forceinline__ float Sq(float gx, float gy) {
    return __fadd_rn(__fmul_rn(gx, gx), __fmul_rn(gy, gy));
}

// Exact reference chain on squared magnitudes (rare path).
__device__ __forceinline__ float slowNms(float sp, float sc, float sn) {
    float mp = __fsqrt_rn(sp), mc = __fsqrt_rn(sc), mn = __fsqrt_rn(sn);
    float e = ((mc >= mp) && (mc >= mn)) ? mc : 0.0f;
    return (e > 0.15f) ? 255.0f : ((e >= 0.05f) ? 0.0f : e);
}

// Squared-domain fast decision (exact outside slow-flagged cases).
__device__ __forceinline__ float fastNms(float sp, float sc, float sn, bool& slow) {
    float mx = fmaxf(sp, sn);
    bool kept   = (sc >= mx);
    bool keptL  = (__fmul_rn(sc, 1.000001f) >= mx);
    bool strong = (sc > 0.0225001f);
    bool hit = kept && strong;
    slow = keptL && !hit;
    return hit ? 255.0f : 0.0f;
}

template <bool GUARD>
__device__ __forceinline__ void tile(const float* __restrict__ x, float* __restrict__ out) {
    const int lane = threadIdx.x & 31;
    const int warp = threadIdx.x >> 5;
    const int c0 = blockIdx.x * CPB + warp * CPW + lane * 4;
    const int r0 = blockIdx.y * ROWS;

    const bool isL = (lane == 0);
    const bool isR = (lane == 31);
    const int hc = isL ? (c0 - 2) : (c0 + 4);
    const bool hok = (isL || isR) && ((unsigned)hc < (unsigned)W);

    const float* p  = x + (size_t)r0 * W + c0;
    const float* ph = x + (size_t)r0 * W + hc;
    const ptrdiff_t dq = (const char*)out - (const char*)x;

    auto ld4 = [&](const float* a, int r) -> float4 {
        if (!GUARD || (unsigned)r < (unsigned)H)
            return *reinterpret_cast<const float4*>(a);
        return make_float4(0.f, 0.f, 0.f, 0.f);
    };
    auto ld2 = [&](const float* a, int r) -> float2 {
        if (hok && (!GUARD || (unsigned)r < (unsigned)H))
            return *reinterpret_cast<const float2*>(a);
        return make_float2(0.f, 0.f);
    };

    float4 xt = ld4(p - W, r0 - 1), xm = ld4(p, r0), xb = ld4(p + W, r0 + 1);
    float2 ht = ld2(ph - W, r0 - 1), hm = ld2(ph, r0), hb = ld2(ph + W, r0 + 1);

#pragma unroll 4
    for (int i = 0; i < ROWS; i++) {
        const int gr = r0 + i;
        float4 xn = ld4(p + 2 * W, gr + 2);      // prefetch row gr+2
        float2 hn = ld2(ph + 2 * W, gr + 2);

        // column sums/diffs
        float A0 = Af(xt.x, xm.x, xb.x), B0 = __fsub_rn(xt.x, xb.x);
        float A1 = Af(xt.y, xm.y, xb.y), B1 = __fsub_rn(xt.y, xb.y);
        float A2 = Af(xt.z, xm.z, xb.z), B2 = __fsub_rn(xt.z, xb.z);
        float A3 = Af(xt.w, xm.w, xb.w), B3 = __fsub_rn(xt.w, xb.w);
        float hA0 = Af(ht.x, hm.x, hb.x), hB0 = __fsub_rn(ht.x, hb.x);
        float hA1 = Af(ht.y, hm.y, hb.y), hB1 = __fsub_rn(ht.y, hb.y);

        // single round of 8 independent shuffles: +/-1 and +/-2 column context
        float Am1 = __shfl_up_sync(0xffffffffu, A3, 1);
        float Bm1 = __shfl_up_sync(0xffffffffu, B3, 1);
        float Am2 = __shfl_up_sync(0xffffffffu, A2, 1);
        float Bm2 = __shfl_up_sync(0xffffffffu, B2, 1);
        float Ap4 = __shfl_down_sync(0xffffffffu, A0, 1);
        float Bp4 = __shfl_down_sync(0xffffffffu, B0, 1);
        float Ap5 = __shfl_down_sync(0xffffffffu, A1, 1);
        float Bp5 = __shfl_down_sync(0xffffffffu, B1, 1);
        if (isL) { Am1 = hA1; Bm1 = hB1; Am2 = hA0; Bm2 = hB0; }
        if (isR) { Ap4 = hA0; Bp4 = hB0; Ap5 = hA1; Bp5 = hB1; }

        // squared magnitudes (sm1/sp4 bitwise == neighbor lane's s3/s0)
        float sm1 = Sq(__fsub_rn(A0, Am2),  GyF(Bm2, Bm1, B0));
        float s0  = Sq(__fsub_rn(A1, Am1),  GyF(Bm1, B0, B1));
        float s1  = Sq(__fsub_rn(A2, A0),   GyF(B0, B1, B2));
        float s2  = Sq(__fsub_rn(A3, A1),   GyF(B1, B2, B3));
        float s3  = Sq(__fsub_rn(Ap4, A2),  GyF(B2, B3, Bp4));
        float sp4 = Sq(__fsub_rn(Ap5, A3),  GyF(B3, Bp4, Bp5));

        bool w0, w1, w2, w3;
        float o0 = fastNms(sm1, s0, s1, w0);
        float o1 = fastNms(s0,  s1, s2, w1);
        float o2 = fastNms(s1,  s2, s3, w2);
        float o3 = fastNms(s2,  s3, sp4, w3);

        bool anySlow = w0 | w1 | w2 | w3;
        if (__any_sync(0xffffffffu, anySlow)) {
            if (w0) o0 = slowNms(sm1, s0, s1);
            if (w1) o1 = slowNms(s0,  s1, s2);
            if (w2) o2 = slowNms(s1,  s2, s3);
            if (w3) o3 = slowNms(s2,  s3, sp4);
        }

        if (GUARD && (gr == 0 || gr == H - 1)) {
            o0 = o1 = o2 = o3 = 0.0f;
        }
        if (c0 == 0) o0 = 0.0f;          // image left border
        if (c0 + 4 == W) o3 = 0.0f;      // image right border

        // evict-first stores: output never re-read
        float* q = (float*)((char*)p + dq);
        __stcs(reinterpret_cast<float4*>(q), make_float4(o0, o1, o2, o3));

        p += W; ph += W;
        xt = xm; xm = xb; xb = xn;
        ht = hm; hm = hb; hb = hn;
    }
}

__global__ void __launch_bounds__(NT, 10) sobel_canny(const float* __restrict__ x,
                                                      float* __restrict__ out) {
    if (blockIdx.y == 0 || blockIdx.y == gridDim.y - 1)
        tile<true>(x, out);
    else
        tile<false>(x, out);
}

}  // namespace

extern "C" void kernel_launch(void* const* d_in, const int* in_sizes, int n_in,
                              void* d_out, int out_size) {
    const float* x = (const float*)d_in[0];
    float* o = (float*)d_out;
    dim3 grid(W / CPB, H / ROWS);   // 8 x 256 = 2048 CTAs
    sobel_canny<<<grid, NT>>>(x, o);
}